// round 12
// baseline (speedup 1.0000x reference)
#include <cuda_runtime.h>
#include <math_constants.h>
#include <cstdint>

// SoftmaxTreeWithLoss on GB300 (sm_103a).
// x: [N=16, C=4096, H=26, W=26] f32; label: [N,26,26] i32 in [0,C)
// Tree: group 0 = channels [0,512) (roots); then 512 groups of 7 children.
// loss_pos = -( child-group logps + x[root] - LSE(root group) ).
//
// R11: the streaming loads in every prior round were 128B-granular with a
// 2704B stride; varying MLP (x10) and warp count (x2.5) never moved BW off
// ~2TB/s -> suspected DRAM-page-locality limit. This round streams channel
// rows SEQUENTIALLY: CTA=(image, 32-ch block), warp = 4 contiguous rows,
// per-position exp partials -> smem merge -> spread atomicAdd into g_S.
// Chain CTAs (same kernel) do the S-independent walk, spin on a done-counter,
// then finish -root_cnt*log(g_S[pos]). One kernel, no serial k2.

#define HW_SZ 676              // 26*26
#define HF2   338              // HW_SZ/2 (float2 per channel row)
#define CN 4096
#define NCB 16                 // 512 root channels / 32 per stream CTA
#define THREADS 256

#define MAX_M (16 * HW_SZ)
__device__ float g_S[MAX_M];                 // per-position exp-sum
__device__ unsigned int g_cnt;               // stream-CTA done counter

__global__ __launch_bounds__(THREADS, 3)
void tree_loss_kernel(const float* __restrict__ x,
                      const int*   __restrict__ label,
                      const int*   __restrict__ group_offsets,
                      const int*   __restrict__ group_sizes,
                      const int*   __restrict__ cid_groups,
                      const int*   __restrict__ parents,
                      float* __restrict__ out,
                      int M, int nStream, float inv_norm)
{
    __shared__ float2 sm[8][HF2];            // per-warp per-position partials
    __shared__ float  red[8];

    const int lane = threadIdx.x & 31;
    const int w    = threadIdx.x >> 5;

    if ((int)blockIdx.x < nStream) {
        // ============ stream CTA: (image n, 32-channel block) ============
        const int n  = blockIdx.x >> 4;
        const int cb = blockIdx.x & 15;
        const int c0 = cb * 32 + w * 4;
        const float2* p = (const float2*)x + ((size_t)n * CN + c0) * HF2;

        float2 acc[11];
        #pragma unroll
        for (int i = 0; i < 11; i++) acc[i] = make_float2(0.f, 0.f);

        #pragma unroll
        for (int ch = 0; ch < 4; ch++) {
            const float2* cp = p + ch * HF2;
            float2 b[11];
            // 11 independent 256B warp-loads, sequential over the row
            #pragma unroll
            for (int i = 0; i < 10; i++) b[i] = cp[lane + 32 * i];
            b[10] = cp[320 + lane];          // overreads into next row: in-bounds, masked
            #pragma unroll
            for (int i = 0; i < 10; i++) {
                acc[i].x += __expf(b[i].x);
                acc[i].y += __expf(b[i].y);
            }
            if (lane < HF2 - 320) {          // 18 valid tail lanes
                acc[10].x += __expf(b[10].x);
                acc[10].y += __expf(b[10].y);
            }
        }

        #pragma unroll
        for (int i = 0; i < 10; i++) sm[w][lane + 32 * i] = acc[i];
        if (lane < HF2 - 320) sm[w][320 + lane] = acc[10];
        __syncthreads();

        // merge 8 warps, spread atomicAdd per position into g_S
        float* gs = g_S + n * HW_SZ;
        for (int e = threadIdx.x; e < HF2; e += THREADS) {
            float sx = 0.f, sy = 0.f;
            #pragma unroll
            for (int q = 0; q < 8; q++) { sx += sm[q][e].x; sy += sm[q][e].y; }
            atomicAdd(&gs[2 * e],     sx);
            atomicAdd(&gs[2 * e + 1], sy);
        }

        __threadfence();
        __syncthreads();
        if (threadIdx.x == 0) atomicAdd(&g_cnt, 1u);
    } else {
        // ============ chain CTA: walk, spin, finish ============
        const int pos = ((int)blockIdx.x - nStream) * THREADS + threadIdx.x;
        const bool valid = pos < M;
        const int n  = valid ? (pos / HW_SZ) : 0;
        const int hw = valid ? (pos - n * HW_SZ) : 0;
        const float* base = x + (size_t)n * (CN * HW_SZ) + hw;

        float child_lp   = 0.f;   // self-contained child-group log-probs
        float root_logit = 0.f;   // group-0 logits on the chain
        float root_cnt   = 0.f;   // # group-0 terms (each needs lse0)

        int cur = valid ? label[pos] : -1;
        #pragma unroll 1
        for (int d = 0; d < 8; d++) {        // MAX_DEPTH = 8
            if (!__ballot_sync(0xffffffffu, cur >= 0)) break;
            if (cur >= 0) {
                const int g = cid_groups[cur];
                if (g == 0) {
                    root_logit += base[cur * HW_SZ];
                    root_cnt   += 1.f;
                } else {
                    const int go = group_offsets[g];
                    const int gs = group_sizes[g];   // 7
                    float ss = 0.f, xv = 0.f;
                    for (int j = 0; j < gs; j++) {
                        const float v = base[(go + j) * HW_SZ];
                        ss += __expf(v);
                        if (go + j == cur) xv = v;
                    }
                    child_lp += xv - __logf(ss);
                }
                cur = parents[cur];
            }
        }

        // wait for all stream CTAs (they never wait on us: deadlock-free)
        if (threadIdx.x == 0) {
            while (*(volatile unsigned int*)&g_cnt < (unsigned int)nStream)
                __nanosleep(200);
        }
        __syncthreads();
        __threadfence();

        float loss = 0.f;
        if (valid) {
            const float S = __ldcg(&g_S[pos]);   // bypass L1: freshly produced
            loss = -(child_lp + root_logit - root_cnt * __logf(S));
        }

        #pragma unroll
        for (int o = 16; o; o >>= 1)
            loss += __shfl_xor_sync(0xffffffffu, loss, o);
        if (lane == 0) red[w] = loss;
        __syncthreads();
        if (w == 0) {
            float t = (lane < 8) ? red[lane] : 0.f;
            #pragma unroll
            for (int o = 4; o; o >>= 1) t += __shfl_xor_sync(0xffffffffu, t, o);
            if (lane == 0) atomicAdd(out, t * inv_norm);
        }
    }
}

extern "C" void kernel_launch(void* const* d_in, const int* in_sizes, int n_in,
                              void* d_out, int out_size)
{
    const float* x     = (const float*)d_in[0];
    const int* label   = (const int*)d_in[1];
    const int* g_off   = (const int*)d_in[2];
    const int* g_sz    = (const int*)d_in[3];
    const int* cid     = (const int*)d_in[4];
    const int* par     = (const int*)d_in[5];
    float* out         = (float*)d_out;

    const int M = in_sizes[1];            // N*H*W
    const int N = M / HW_SZ;              // batch size
    const float inv_norm = 1.0f / (float)N;

    void* gS_addr = nullptr;
    void* gC_addr = nullptr;
    cudaGetSymbolAddress(&gS_addr, g_S);
    cudaGetSymbolAddress(&gC_addr, g_cnt);
    cudaMemsetAsync(gS_addr, 0, (size_t)M * sizeof(float));
    cudaMemsetAsync(gC_addr, 0, sizeof(unsigned int));
    cudaMemsetAsync(d_out, 0, sizeof(float));

    const int nStream     = N * NCB;                       // 256
    const int chainBlocks = (M + THREADS - 1) / THREADS;   // 43
    tree_loss_kernel<<<nStream + chainBlocks, THREADS>>>(
        x, label, g_off, g_sz, cid, par, out, M, nStream, inv_norm);
}

// round 14
// speedup vs baseline: 1.7344x; 1.7344x over previous
#include <cuda_runtime.h>
#include <math_constants.h>
#include <cstdint>

// SoftmaxTreeWithLoss on GB300 (sm_103a).
// x: [N=16, C=4096, H=26, W=26] f32; label: [N,26,26] i32 in [0,C)
// Tree: group 0 = channels [0,512) (roots); then 512 groups of 7 children.
// loss_pos = -( child-group logps + x[root] - LSE(root group) ).
//
// R13: retry the TMA-path experiment WITHOUT a tensor map (R12 faulted,
// almost certainly in host-side descriptor encoding). Each stream warp issues
// 64 x 128B 1D cp.async.bulk copies (2 per lane) -- contiguous 16B-aligned
// runs -- into its 8KB smem chunk against its own mbarrier (expect_tx=8KB).
// Bulk-async engine does the fetching: bypasses the per-warp LDG scoreboard
// path that pinned every prior kernel at ~2-2.6TB/s. Consumption + chain
// warp identical to R6/R12.

#define HW_SZ 676
#define NBOX 22                // 21 full 32-pos boxes + 1 tail box per image
#define NW_STREAM 8
#define CH_PER_WARP 64
#define THREADS 288            // 8 stream + 1 chain warp
#define CHUNK_FLOATS (CH_PER_WARP * 32)          // 2048
#define CHUNK_BYTES  (CHUNK_FLOATS * 4)          // 8192
#define DSMEM_BYTES  (NW_STREAM * CHUNK_BYTES)   // 65536

__device__ __forceinline__ uint32_t smem_u32(const void* p) {
    return (uint32_t)__cvta_generic_to_shared(p);
}

__global__ __launch_bounds__(THREADS, 3)
void tree_loss_kernel(const float* __restrict__ x,
                      const int*   __restrict__ label,
                      const int*   __restrict__ group_offsets,
                      const int*   __restrict__ group_sizes,
                      const int*   __restrict__ cid_groups,
                      const int*   __restrict__ parents,
                      float* __restrict__ out,
                      int M, int Cn, float inv_norm)
{
    extern __shared__ float tile[];                       // 8 x [64ch][32pos]
    __shared__ __align__(8) unsigned long long mbar[NW_STREAM];
    __shared__ float sm_s[NW_STREAM][32];

    const int lane = threadIdx.x & 31;
    const int w    = threadIdx.x >> 5;

    const int b   = blockIdx.x;
    const int n   = b / NBOX;
    const int j   = b - n * NBOX;
    const int hw0 = (j < NBOX - 1) ? j * 32 : (HW_SZ - 32);   // tail at 644

    // ---- thread 0: init the 8 mbarriers, fence generic->async proxy ----
    if (threadIdx.x == 0) {
        #pragma unroll
        for (int i = 0; i < NW_STREAM; i++)
            asm volatile("mbarrier.init.shared.b64 [%0], 1;"
                         :: "r"(smem_u32(&mbar[i])) : "memory");
        asm volatile("fence.proxy.async.shared::cta;" ::: "memory");
    }
    __syncthreads();

    if (w < NW_STREAM) {
        // ---- stream warp w: issue 64 x 128B bulk copies, wait, reduce ----
        const uint32_t mb = smem_u32(&mbar[w]);
        if (lane == 0)
            asm volatile("mbarrier.arrive.expect_tx.shared.b64 _, [%0], %1;"
                         :: "r"(mb), "r"((uint32_t)CHUNK_BYTES) : "memory");
        __syncwarp();

        // lane issues channel rows (2*lane) and (2*lane+1) of this warp's 64
        {
            const int ch = w * CH_PER_WARP + 2 * lane;
            const float* src = x + ((size_t)(n * Cn + ch)) * HW_SZ + hw0;
            uint32_t dst = smem_u32(tile + w * CHUNK_FLOATS) + (2 * lane) * 128;
            asm volatile(
                "cp.async.bulk.shared::cta.global.mbarrier::complete_tx::bytes"
                " [%0], [%1], %2, [%3];"
                :: "r"(dst), "l"(src), "r"(128u), "r"(mb) : "memory");
            asm volatile(
                "cp.async.bulk.shared::cta.global.mbarrier::complete_tx::bytes"
                " [%0], [%1], %2, [%3];"
                :: "r"(dst + 128u), "l"(src + HW_SZ), "r"(128u), "r"(mb)
                : "memory");
        }

        // wait for this warp's 8KB chunk
        {
            uint32_t done;
            do {
                asm volatile(
                    "{\n\t.reg .pred p;\n\t"
                    "mbarrier.try_wait.parity.acquire.cta.shared::cta.b64 p, [%1], 0, 0x989680;\n\t"
                    "selp.b32 %0, 1, 0, p;\n\t}"
                    : "=r"(done) : "r"(mb) : "memory");
            } while (!done);
        }

        const float* buf = tile + w * CHUNK_FLOATS;   // [64][32], conflict-free
        float a0 = 0.f, a1 = 0.f, a2 = 0.f, a3 = 0.f;
        #pragma unroll
        for (int c = 0; c < CH_PER_WARP; c += 4) {
            a0 += __expf(buf[(c + 0) * 32 + lane]);
            a1 += __expf(buf[(c + 1) * 32 + lane]);
            a2 += __expf(buf[(c + 2) * 32 + lane]);
            a3 += __expf(buf[(c + 3) * 32 + lane]);
        }
        sm_s[w][lane] = (a0 + a1) + (a2 + a3);
        __syncthreads();
    } else {
        // ---- chain warp: parent-chain walk via LDG, overlapped ----
        const int hw  = hw0 + lane;
        const int pos = n * HW_SZ + hw;
        // tail box overlaps the previous one: it owns only lanes 28..31
        const bool valid = (pos < M) && (j < NBOX - 1 || lane >= 28);
        const float* base = x + (size_t)n * ((size_t)Cn * HW_SZ) + hw;

        float child_lp   = 0.f;
        float root_logit = 0.f;
        float root_cnt   = 0.f;

        int cur = valid ? label[pos] : -1;
        #pragma unroll 1
        for (int d = 0; d < 8; d++) {            // MAX_DEPTH = 8
            if (!__ballot_sync(0xffffffffu, cur >= 0)) break;
            if (cur >= 0) {
                const int g = cid_groups[cur];
                if (g == 0) {
                    root_logit += base[cur * HW_SZ];
                    root_cnt   += 1.f;
                } else {
                    const int go = group_offsets[g];
                    const int gs = group_sizes[g];   // 7
                    float ss = 0.f, xv = 0.f;
                    for (int jj = 0; jj < gs; jj++) {
                        const float v = base[(go + jj) * HW_SZ];
                        ss += __expf(v);
                        if (go + jj == cur) xv = v;
                    }
                    child_lp += xv - __logf(ss);
                }
                cur = parents[cur];
            }
        }

        __syncthreads();

        float S = 0.f;
        #pragma unroll
        for (int q = 0; q < NW_STREAM; q++) S += sm_s[q][lane];

        float loss = 0.f;
        if (valid)
            loss = -(child_lp + root_logit - root_cnt * __logf(S));

        #pragma unroll
        for (int o = 16; o; o >>= 1)
            loss += __shfl_xor_sync(0xffffffffu, loss, o);
        if (lane == 0)
            atomicAdd(out, loss * inv_norm);
    }
}

extern "C" void kernel_launch(void* const* d_in, const int* in_sizes, int n_in,
                              void* d_out, int out_size)
{
    const float* x     = (const float*)d_in[0];
    const int* label   = (const int*)d_in[1];
    const int* g_off   = (const int*)d_in[2];
    const int* g_sz    = (const int*)d_in[3];
    const int* cid     = (const int*)d_in[4];
    const int* par     = (const int*)d_in[5];
    float* out         = (float*)d_out;

    const int M  = in_sizes[1];             // N*H*W
    const int N  = M / HW_SZ;               // batch size
    const int Cn = in_sizes[0] / M;         // 4096
    const float inv_norm = 1.0f / (float)N;

    static bool attr_done = false;
    if (!attr_done) {
        cudaFuncSetAttribute(tree_loss_kernel,
                             cudaFuncAttributeMaxDynamicSharedMemorySize,
                             DSMEM_BYTES);
        attr_done = true;
    }

    cudaMemsetAsync(d_out, 0, sizeof(float));

    const int blocks = N * NBOX;            // 352
    tree_loss_kernel<<<blocks, THREADS, DSMEM_BYTES>>>(
        x, label, g_off, g_sz, cid, par, out, M, Cn, inv_norm);
}